// round 13
// baseline (speedup 1.0000x reference)
#include <cuda_runtime.h>
#include <math.h>

#define RES      256
#define NTRI     1000
#define NBATCH   2
#define NBT      (NBATCH * NTRI)
#define EPSF     1e-8f
#define NPIX     (RES * RES)
#define TIL      8                    // tile edge (px)
#define TPA      (RES / TIL)          // tiles per axis = 32
#define NTILE    (TPA * TPA)          // 1024 tiles per batch
#define CHUNK    64                   // triangles staged in smem per pass

// per-(b,t) params: q0={A0,B0,C0,A1} q1={B1,C1,A2,B2} q2={C2,mn,inv,unused}
__device__ float4 g_q[NBT * 3];
__device__ int4   g_bb[NBT];
// per-(b,tile) triangle lists (ascending t, order-preserving)
__device__ int    g_cnt[NBATCH * NTILE];
__device__ int    g_list[NBATCH * NTILE * NTRI];

struct Coef { float A0,B0,C0, A1,B1,C1, A2,B2,C2; };

__device__ __forceinline__ float eval_s(const Coef& c, float fx, float fy)
{
    float t0 = fmaxf(fmaf(c.C0, fy, fmaf(c.B0, fx, c.A0)), 0.0f);
    float t1 = fmaxf(fmaf(c.C1, fy, fmaf(c.B1, fx, c.A1)), 0.0f);
    float t2 = fmaxf(fmaf(c.C2, fy, fmaf(c.B2, fx, c.A2)), 0.0f);
    return t0 * t1 * t2;
}

// (5,4) continued-fraction Pade tanh, err <= ~2.4e-5 on [0, 1.05]
__device__ __forceinline__ float tanh_pade(float x)
{
    float t   = x * x;
    float num = fmaf(t, fmaf(t, 1.0f, 105.0f), 945.0f);
    float den = fmaf(t, fmaf(t, 15.0f, 420.0f), 945.0f);
    return x * __fdividef(num, den);
}

// exact grid max over row y within [bb.x, bb.y] (log-concave -> candidates)
__device__ float row_max(const Coef& c, const Coef& n, const int4 bb, int y)
{
    const float fy = (float)y;
    float a0 = fmaf(n.C0, fy, n.A0);
    float a1 = fmaf(n.C1, fy, n.A1);
    float a2 = fmaf(n.C2, fy, n.A2);

    float lo = (float)bb.x, hi = (float)bb.y;
    bool ok = true;
    if (n.B0 >  1e-25f)      lo = fmaxf(lo, -__fdividef(a0, n.B0));
    else if (n.B0 < -1e-25f) hi = fminf(hi, -__fdividef(a0, n.B0));
    else                     ok = ok && (a0 > 0.0f);
    if (n.B1 >  1e-25f)      lo = fmaxf(lo, -__fdividef(a1, n.B1));
    else if (n.B1 < -1e-25f) hi = fminf(hi, -__fdividef(a1, n.B1));
    else                     ok = ok && (a1 > 0.0f);
    if (n.B2 >  1e-25f)      lo = fmaxf(lo, -__fdividef(a2, n.B2));
    else if (n.B2 < -1e-25f) hi = fminf(hi, -__fdividef(a2, n.B2));
    else                     ok = ok && (a2 > 0.0f);

    float clo = ceilf(lo), chi = floorf(hi);
    if (!ok || clo > chi) return 0.0f;

    float q2 = 3.0f * n.B0 * n.B1 * n.B2;
    float q1 = 2.0f * (n.B0*n.B1*a2 + n.B0*n.B2*a1 + n.B1*n.B2*a0);
    float q0 = n.B0*a1*a2 + n.B1*a0*a2 + n.B2*a0*a1;

    float xc1 = 0.5f * (clo + chi), xc2 = xc1;
    if (fabsf(q2) > 1e-30f) {
        float disc = fmaf(q1, q1, -4.0f * q2 * q0);
        float sq   = sqrtf(fmaxf(disc, 0.0f));
        float i2   = __fdividef(0.5f, q2);
        xc1 = (-q1 + sq) * i2;
        xc2 = (-q1 - sq) * i2;
    } else if (fabsf(q1) > 1e-30f) {
        xc1 = xc2 = -__fdividef(q0, q1);
    }

    float f1 = floorf(xc1), f2 = floorf(xc2);
    float cand[6] = { clo, chi, f1, f1 + 1.0f, f2, f2 + 1.0f };
    float m = 0.0f;
    #pragma unroll
    for (int i = 0; i < 6; i++) {
        float x = fminf(fmaxf(cand[i], clo), chi);   // NaN-safe
        m = fmaxf(m, eval_s(c, x, fy));
    }
    return m;
}

// ---------------------------------------------------------------------------
// Kernel 1: one warp per (b,t). All lanes redundantly compute coefficients,
// then split the analytic row-max across lanes. (unchanged from R8)
// ---------------------------------------------------------------------------
__global__ void __launch_bounds__(256) setup_kernel(const float* __restrict__ meshes,
                                                    const float* __restrict__ K,
                                                    const int*   __restrict__ model_idxs,
                                                    const float* __restrict__ poses)
{
    const int bt = (blockIdx.x * blockDim.x + threadIdx.x) >> 5;
    if (bt >= NBT) return;
    const int lane = threadIdx.x & 31;
    const int b = bt / NTRI;
    const int t = bt - b * NTRI;

    float M[12];
    const float* cam = poses + b * 12;
    #pragma unroll
    for (int r = 0; r < 3; r++)
        #pragma unroll
        for (int cc = 0; cc < 4; cc++) {
            float s = 0.0f;
            #pragma unroll
            for (int k = 0; k < 3; k++)
                s += K[r * 3 + k] * cam[k * 4 + cc];
            M[r * 4 + cc] = s;
        }

    const float* mesh = meshes + ((size_t)model_idxs[b] * NTRI + t) * 9;
    float vx[3], vy[3];
    #pragma unroll
    for (int j = 0; j < 3; j++) {
        float X = mesh[j*3+0], Y = mesh[j*3+1], Z = mesh[j*3+2];
        float x = M[0]*X + M[1]*Y + M[2] *Z + M[3];
        float y = M[4]*X + M[5]*Y + M[6] *Z + M[7];
        float w = M[8]*X + M[9]*Y + M[10]*Z + M[11];
        float iw = 1.0f / (w + EPSF);
        vx[j] = x * iw;  vy[j] = y * iw;
    }

    const float e0x = vx[1]-vx[0], e0y = vy[1]-vy[0];
    const float e1x = vx[2]-vx[1], e1y = vy[2]-vy[1];
    const float e2x = vx[0]-vx[2], e2y = vy[0]-vy[2];
    const float N = e0x * e2y - e0y * e2x + EPSF;

    Coef c;
    c.A0 = N*(e0x*vy[0]-e0y*vx[0]); c.B0 =  N*e0y; c.C0 = -N*e0x;
    c.A1 = N*(e1x*vy[1]-e1y*vx[1]); c.B1 =  N*e1y; c.C1 = -N*e1x;
    c.A2 = N*(e2x*vy[2]-e2y*vx[2]); c.B2 =  N*e2y; c.C2 = -N*e2x;

    bool inter = true;
    #pragma unroll
    for (int k = 0; k < 4; k++) {
        float cx = (k & 1) ? (float)(RES-1) : 0.0f;
        float cy = (k & 2) ? (float)(RES-1) : 0.0f;
        inter = inter && (fmaf(c.C0, cy, fmaf(c.B0, cx, c.A0)) > 0.0f)
                      && (fmaf(c.C1, cy, fmaf(c.B1, cx, c.A1)) > 0.0f)
                      && (fmaf(c.C2, cy, fmaf(c.B2, cx, c.A2)) > 0.0f);
    }

    float fx0 = fminf(fminf(vx[0],vx[1]),vx[2]) - 1.0f;
    float fx1 = fmaxf(fmaxf(vx[0],vx[1]),vx[2]) + 1.0f;
    float fy0 = fminf(fminf(vy[0],vy[1]),vy[2]) - 1.0f;
    float fy1 = fmaxf(fmaxf(vy[0],vy[1]),vy[2]) + 1.0f;
    bool safe = isfinite(fx0) && isfinite(fx1) && isfinite(fy0) && isfinite(fy1)
                && fabsf(N) > 1e-6f;
    int4 bb;
    if (safe) {
        int x0 = (fx0 < 0.0f) ? 0 : ((fx0 > (float)(RES-1)) ? RES : (int)fx0);
        int x1 = (fx1 > (float)(RES-1)) ? (RES-1) : ((fx1 < 0.0f) ? -1 : (int)fx1);
        int y0 = (fy0 < 0.0f) ? 0 : ((fy0 > (float)(RES-1)) ? RES : (int)fy0);
        int y1 = (fy1 > (float)(RES-1)) ? (RES-1) : ((fy1 < 0.0f) ? -1 : (int)fy1);
        if (x0 > x1 || y0 > y1) { x0 = RES; x1 = -1; y0 = RES; y1 = -1; }
        bb = make_int4(x0, x1, y0, y1);
    } else {
        bb = make_int4(0, RES-1, 0, RES-1);
    }

    // normalized coeffs for the root math (scale-invariant)
    float kap = 0.0f;
    kap = fmaxf(kap, fabsf(c.A0)); kap = fmaxf(kap, 256.0f*fabsf(c.B0)); kap = fmaxf(kap, 256.0f*fabsf(c.C0));
    kap = fmaxf(kap, fabsf(c.A1)); kap = fmaxf(kap, 256.0f*fabsf(c.B1)); kap = fmaxf(kap, 256.0f*fabsf(c.C1));
    kap = fmaxf(kap, fabsf(c.A2)); kap = fmaxf(kap, 256.0f*fabsf(c.B2)); kap = fmaxf(kap, 256.0f*fabsf(c.C2));
    float rk = (kap > 1e-30f) ? (1.0f / kap) : 0.0f;
    Coef n;
    n.A0 = c.A0*rk; n.B0 = c.B0*rk; n.C0 = c.C0*rk;
    n.A1 = c.A1*rk; n.B1 = c.B1*rk; n.C1 = c.C1*rk;
    n.A2 = c.A2*rk; n.B2 = c.B2*rk; n.C2 = c.C2*rk;

    float mx = 0.0f;
    for (int y = bb.z + lane; y <= bb.w; y += 32)
        mx = fmaxf(mx, row_max(c, n, bb, y));
    #pragma unroll
    for (int o = 16; o > 0; o >>= 1)
        mx = fmaxf(mx, __shfl_xor_sync(0xffffffffu, mx, o));

    if (lane == 0) {
        float mn = 0.0f;
        if (inter) {   // quasi-concave => grid min at an image corner
            const float e = (float)(RES - 1);
            mn = eval_s(c, 0.0f, 0.0f);
            mn = fminf(mn, eval_s(c, e, 0.0f));
            mn = fminf(mn, eval_s(c, 0.0f, e));
            mn = fminf(mn, eval_s(c, e, e));
        }
        float inv = 1.0f / (mx - mn + EPSF);
        g_q[bt*3+0] = make_float4(c.A0, c.B0, c.C0, c.A1);
        g_q[bt*3+1] = make_float4(c.B1, c.C1, c.A2, c.B2);
        g_q[bt*3+2] = make_float4(c.C2, mn,   inv,  0.0f);
        g_bb[bt]    = bb;
    }
}

// ---------------------------------------------------------------------------
// Kernel 2: deterministic, order-preserving 8x8 tile binning.
// One warp per (b, tile); ballot-compaction keeps triangle order ascending.
// Skipped (tri,px) pairs contribute exactly tanh(0)=0 in the reference.
// ---------------------------------------------------------------------------
__global__ void __launch_bounds__(256) bin_kernel()
{
    const int gw = (blockIdx.x * blockDim.x + threadIdx.x) >> 5;
    if (gw >= NBATCH * NTILE) return;
    const int lane = threadIdx.x & 31;

    const int b  = gw / NTILE;
    const int tt = gw - b * NTILE;
    const int xlo = (tt >> 5) * TIL, xhi = xlo + TIL - 1;
    const int ylo = (tt & 31) * TIL, yhi = ylo + TIL - 1;

    const int4* __restrict__ bb = g_bb + b * NTRI;
    int* __restrict__ list = g_list + (size_t)gw * NTRI;

    int cnt = 0;
    for (int base = 0; base < NTRI; base += 32) {
        const int t = base + lane;
        bool ok = false;
        if (t < NTRI) {
            int4 B = bb[t];
            ok = (B.x <= xhi) && (B.y >= xlo) && (B.z <= yhi) && (B.w >= ylo);
        }
        unsigned m = __ballot_sync(0xffffffffu, ok);
        if (ok) list[cnt + __popc(m & ((1u << lane) - 1u))] = t;
        cnt += __popc(m);
    }
    if (lane == 0) g_cnt[gw] = cnt;
}

// ---------------------------------------------------------------------------
// Kernel 3: gather. Block = 64 threads = one 8x8 tile, 1 px/thread.
// Register accumulation (NO atomics, NO fixed point), triangle params staged
// in SMEM in chunks. Deterministic: ascending t order every replay.
// ---------------------------------------------------------------------------
__global__ void __launch_bounds__(64) gather_kernel(float* __restrict__ out)
{
    __shared__ float4 sQ[CHUNK * 3];

    const int tt  = blockIdx.x;
    const int b   = blockIdx.y;
    const int tid = threadIdx.x;

    const int px = (tt >> 5) * TIL + (tid >> 3);
    const int py = (tt & 31) * TIL + (tid & 7);
    const float fx = (float)px, fy = (float)py;

    const int gw  = b * NTILE + tt;
    const int cnt = g_cnt[gw];
    const int* __restrict__ list = g_list + (size_t)gw * NTRI;

    float acc = 0.0f;

    for (int base = 0; base < cnt; base += CHUNK) {
        const int m = min(CHUNK, cnt - base);
        if (tid < m) {
            const int t3 = (b * NTRI + list[base + tid]) * 3;
            sQ[tid*3+0] = g_q[t3+0];
            sQ[tid*3+1] = g_q[t3+1];
            sQ[tid*3+2] = g_q[t3+2];
        }
        __syncthreads();

        if (m == CHUNK) {
            #pragma unroll 4
            for (int i = 0; i < CHUNK; i++) {
                float4 q0 = sQ[i*3+0], q1 = sQ[i*3+1], q2 = sQ[i*3+2];
                float u0 = fmaxf(fmaf(q0.z, fy, fmaf(q0.y, fx, q0.x)), 0.0f);
                float u1 = fmaxf(fmaf(q1.y, fy, fmaf(q1.x, fx, q0.w)), 0.0f);
                float u2 = fmaxf(fmaf(q2.x, fy, fmaf(q1.w, fx, q1.z)), 0.0f);
                float d  = u0 * u1 * u2 - q2.y;
                if (d > 0.0f) acc += tanh_pade(d * q2.z);
            }
        } else {
            for (int i = 0; i < m; i++) {
                float4 q0 = sQ[i*3+0], q1 = sQ[i*3+1], q2 = sQ[i*3+2];
                float u0 = fmaxf(fmaf(q0.z, fy, fmaf(q0.y, fx, q0.x)), 0.0f);
                float u1 = fmaxf(fmaf(q1.y, fy, fmaf(q1.x, fx, q0.w)), 0.0f);
                float u2 = fmaxf(fmaf(q2.x, fy, fmaf(q1.w, fx, q1.z)), 0.0f);
                float d  = u0 * u1 * u2 - q2.y;
                if (d > 0.0f) acc += tanh_pade(d * q2.z);
            }
        }
        __syncthreads();
    }

    out[(size_t)b * NPIX + px * RES + py] = acc;
}

// ---------------------------------------------------------------------------
extern "C" void kernel_launch(void* const* d_in, const int* in_sizes, int n_in,
                              void* d_out, int out_size)
{
    const float* meshes = (const float*)d_in[0];
    const float* K      = (const float*)d_in[1];
    const int*   idxs   = (const int*)  d_in[2];
    const float* poses  = (const float*)d_in[3];
    float*       out    = (float*)d_out;

    setup_kernel<<<(NBT * 32 + 255) / 256, 256>>>(meshes, K, idxs, poses);
    bin_kernel<<<(NBATCH * NTILE * 32 + 255) / 256, 256>>>();

    dim3 g(NTILE, NBATCH);
    gather_kernel<<<g, 64>>>(out);
}

// round 15
// speedup vs baseline: 1.4304x; 1.4304x over previous
#include <cuda_runtime.h>
#include <math.h>

#define RES      256
#define NTRI     1000
#define NBATCH   2
#define NBT      (NBATCH * NTRI)
#define EPSF     1e-8f
#define NPIX     (RES * RES)
#define TIL      8                    // tile edge (px)
#define TPA      (RES / TIL)          // tiles per axis = 32
#define NTILE    (TPA * TPA)          // 1024 tiles per batch
#define NSEG     8                    // triangle-list segments per tile
#define SEGCAP   128                  // >= ceil(NTRI/NSEG) = 125

// per-(b,t) params: q0={A0,B0,C0,A1} q1={B1,C1,A2,B2} q2={C2,mn,inv,unused}
__device__ float4 g_q[NBT * 3];
__device__ int4   g_bb[NBT];
// per-(b,tile) triangle lists (ascending t, order-preserving)
__device__ int    g_cnt[NBATCH * NTILE];
__device__ int    g_list[NBATCH * NTILE * NTRI];
// split-K partial sums: [(b*NSEG+s)*NTILE + tile]*64 + tid   (4 MB)
__device__ float  g_part[NBATCH * NSEG * NTILE * 64];

struct Coef { float A0,B0,C0, A1,B1,C1, A2,B2,C2; };

__device__ __forceinline__ float eval_s(const Coef& c, float fx, float fy)
{
    float t0 = fmaxf(fmaf(c.C0, fy, fmaf(c.B0, fx, c.A0)), 0.0f);
    float t1 = fmaxf(fmaf(c.C1, fy, fmaf(c.B1, fx, c.A1)), 0.0f);
    float t2 = fmaxf(fmaf(c.C2, fy, fmaf(c.B2, fx, c.A2)), 0.0f);
    return t0 * t1 * t2;
}

// (5,4) continued-fraction Pade tanh, err <= ~2.4e-5 on [0, 1.05]
__device__ __forceinline__ float tanh_pade(float x)
{
    float t   = x * x;
    float num = fmaf(t, fmaf(t, 1.0f, 105.0f), 945.0f);
    float den = fmaf(t, fmaf(t, 15.0f, 420.0f), 945.0f);
    return x * __fdividef(num, den);
}

// exact grid max over row y within [bb.x, bb.y] (log-concave -> candidates)
__device__ float row_max(const Coef& c, const Coef& n, const int4 bb, int y)
{
    const float fy = (float)y;
    float a0 = fmaf(n.C0, fy, n.A0);
    float a1 = fmaf(n.C1, fy, n.A1);
    float a2 = fmaf(n.C2, fy, n.A2);

    float lo = (float)bb.x, hi = (float)bb.y;
    bool ok = true;
    if (n.B0 >  1e-25f)      lo = fmaxf(lo, -__fdividef(a0, n.B0));
    else if (n.B0 < -1e-25f) hi = fminf(hi, -__fdividef(a0, n.B0));
    else                     ok = ok && (a0 > 0.0f);
    if (n.B1 >  1e-25f)      lo = fmaxf(lo, -__fdividef(a1, n.B1));
    else if (n.B1 < -1e-25f) hi = fminf(hi, -__fdividef(a1, n.B1));
    else                     ok = ok && (a1 > 0.0f);
    if (n.B2 >  1e-25f)      lo = fmaxf(lo, -__fdividef(a2, n.B2));
    else if (n.B2 < -1e-25f) hi = fminf(hi, -__fdividef(a2, n.B2));
    else                     ok = ok && (a2 > 0.0f);

    float clo = ceilf(lo), chi = floorf(hi);
    if (!ok || clo > chi) return 0.0f;

    float q2 = 3.0f * n.B0 * n.B1 * n.B2;
    float q1 = 2.0f * (n.B0*n.B1*a2 + n.B0*n.B2*a1 + n.B1*n.B2*a0);
    float q0 = n.B0*a1*a2 + n.B1*a0*a2 + n.B2*a0*a1;

    float xc1 = 0.5f * (clo + chi), xc2 = xc1;
    if (fabsf(q2) > 1e-30f) {
        float disc = fmaf(q1, q1, -4.0f * q2 * q0);
        float sq   = sqrtf(fmaxf(disc, 0.0f));
        float i2   = __fdividef(0.5f, q2);
        xc1 = (-q1 + sq) * i2;
        xc2 = (-q1 - sq) * i2;
    } else if (fabsf(q1) > 1e-30f) {
        xc1 = xc2 = -__fdividef(q0, q1);
    }

    float f1 = floorf(xc1), f2 = floorf(xc2);
    float cand[6] = { clo, chi, f1, f1 + 1.0f, f2, f2 + 1.0f };
    float m = 0.0f;
    #pragma unroll
    for (int i = 0; i < 6; i++) {
        float x = fminf(fmaxf(cand[i], clo), chi);   // NaN-safe
        m = fmaxf(m, eval_s(c, x, fy));
    }
    return m;
}

// ---------------------------------------------------------------------------
// Kernel 1: one warp per (b,t). (unchanged from R8)
// ---------------------------------------------------------------------------
__global__ void __launch_bounds__(256) setup_kernel(const float* __restrict__ meshes,
                                                    const float* __restrict__ K,
                                                    const int*   __restrict__ model_idxs,
                                                    const float* __restrict__ poses)
{
    const int bt = (blockIdx.x * blockDim.x + threadIdx.x) >> 5;
    if (bt >= NBT) return;
    const int lane = threadIdx.x & 31;
    const int b = bt / NTRI;
    const int t = bt - b * NTRI;

    float M[12];
    const float* cam = poses + b * 12;
    #pragma unroll
    for (int r = 0; r < 3; r++)
        #pragma unroll
        for (int cc = 0; cc < 4; cc++) {
            float s = 0.0f;
            #pragma unroll
            for (int k = 0; k < 3; k++)
                s += K[r * 3 + k] * cam[k * 4 + cc];
            M[r * 4 + cc] = s;
        }

    const float* mesh = meshes + ((size_t)model_idxs[b] * NTRI + t) * 9;
    float vx[3], vy[3];
    #pragma unroll
    for (int j = 0; j < 3; j++) {
        float X = mesh[j*3+0], Y = mesh[j*3+1], Z = mesh[j*3+2];
        float x = M[0]*X + M[1]*Y + M[2] *Z + M[3];
        float y = M[4]*X + M[5]*Y + M[6] *Z + M[7];
        float w = M[8]*X + M[9]*Y + M[10]*Z + M[11];
        float iw = 1.0f / (w + EPSF);
        vx[j] = x * iw;  vy[j] = y * iw;
    }

    const float e0x = vx[1]-vx[0], e0y = vy[1]-vy[0];
    const float e1x = vx[2]-vx[1], e1y = vy[2]-vy[1];
    const float e2x = vx[0]-vx[2], e2y = vy[0]-vy[2];
    const float N = e0x * e2y - e0y * e2x + EPSF;

    Coef c;
    c.A0 = N*(e0x*vy[0]-e0y*vx[0]); c.B0 =  N*e0y; c.C0 = -N*e0x;
    c.A1 = N*(e1x*vy[1]-e1y*vx[1]); c.B1 =  N*e1y; c.C1 = -N*e1x;
    c.A2 = N*(e2x*vy[2]-e2y*vx[2]); c.B2 =  N*e2y; c.C2 = -N*e2x;

    bool inter = true;
    #pragma unroll
    for (int k = 0; k < 4; k++) {
        float cx = (k & 1) ? (float)(RES-1) : 0.0f;
        float cy = (k & 2) ? (float)(RES-1) : 0.0f;
        inter = inter && (fmaf(c.C0, cy, fmaf(c.B0, cx, c.A0)) > 0.0f)
                      && (fmaf(c.C1, cy, fmaf(c.B1, cx, c.A1)) > 0.0f)
                      && (fmaf(c.C2, cy, fmaf(c.B2, cx, c.A2)) > 0.0f);
    }

    float fx0 = fminf(fminf(vx[0],vx[1]),vx[2]) - 1.0f;
    float fx1 = fmaxf(fmaxf(vx[0],vx[1]),vx[2]) + 1.0f;
    float fy0 = fminf(fminf(vy[0],vy[1]),vy[2]) - 1.0f;
    float fy1 = fmaxf(fmaxf(vy[0],vy[1]),vy[2]) + 1.0f;
    bool safe = isfinite(fx0) && isfinite(fx1) && isfinite(fy0) && isfinite(fy1)
                && fabsf(N) > 1e-6f;
    int4 bb;
    if (safe) {
        int x0 = (fx0 < 0.0f) ? 0 : ((fx0 > (float)(RES-1)) ? RES : (int)fx0);
        int x1 = (fx1 > (float)(RES-1)) ? (RES-1) : ((fx1 < 0.0f) ? -1 : (int)fx1);
        int y0 = (fy0 < 0.0f) ? 0 : ((fy0 > (float)(RES-1)) ? RES : (int)fy0);
        int y1 = (fy1 > (float)(RES-1)) ? (RES-1) : ((fy1 < 0.0f) ? -1 : (int)fy1);
        if (x0 > x1 || y0 > y1) { x0 = RES; x1 = -1; y0 = RES; y1 = -1; }
        bb = make_int4(x0, x1, y0, y1);
    } else {
        bb = make_int4(0, RES-1, 0, RES-1);
    }

    float kap = 0.0f;
    kap = fmaxf(kap, fabsf(c.A0)); kap = fmaxf(kap, 256.0f*fabsf(c.B0)); kap = fmaxf(kap, 256.0f*fabsf(c.C0));
    kap = fmaxf(kap, fabsf(c.A1)); kap = fmaxf(kap, 256.0f*fabsf(c.B1)); kap = fmaxf(kap, 256.0f*fabsf(c.C1));
    kap = fmaxf(kap, fabsf(c.A2)); kap = fmaxf(kap, 256.0f*fabsf(c.B2)); kap = fmaxf(kap, 256.0f*fabsf(c.C2));
    float rk = (kap > 1e-30f) ? (1.0f / kap) : 0.0f;
    Coef n;
    n.A0 = c.A0*rk; n.B0 = c.B0*rk; n.C0 = c.C0*rk;
    n.A1 = c.A1*rk; n.B1 = c.B1*rk; n.C1 = c.C1*rk;
    n.A2 = c.A2*rk; n.B2 = c.B2*rk; n.C2 = c.C2*rk;

    float mx = 0.0f;
    for (int y = bb.z + lane; y <= bb.w; y += 32)
        mx = fmaxf(mx, row_max(c, n, bb, y));
    #pragma unroll
    for (int o = 16; o > 0; o >>= 1)
        mx = fmaxf(mx, __shfl_xor_sync(0xffffffffu, mx, o));

    if (lane == 0) {
        float mn = 0.0f;
        if (inter) {   // quasi-concave => grid min at an image corner
            const float e = (float)(RES - 1);
            mn = eval_s(c, 0.0f, 0.0f);
            mn = fminf(mn, eval_s(c, e, 0.0f));
            mn = fminf(mn, eval_s(c, 0.0f, e));
            mn = fminf(mn, eval_s(c, e, e));
        }
        float inv = 1.0f / (mx - mn + EPSF);
        g_q[bt*3+0] = make_float4(c.A0, c.B0, c.C0, c.A1);
        g_q[bt*3+1] = make_float4(c.B1, c.C1, c.A2, c.B2);
        g_q[bt*3+2] = make_float4(c.C2, mn,   inv,  0.0f);
        g_bb[bt]    = bb;
    }
}

// ---------------------------------------------------------------------------
// Kernel 2: deterministic, order-preserving 8x8 tile binning (unchanged).
// ---------------------------------------------------------------------------
__global__ void __launch_bounds__(256) bin_kernel()
{
    const int gw = (blockIdx.x * blockDim.x + threadIdx.x) >> 5;
    if (gw >= NBATCH * NTILE) return;
    const int lane = threadIdx.x & 31;

    const int b  = gw / NTILE;
    const int tt = gw - b * NTILE;
    const int xlo = (tt >> 5) * TIL, xhi = xlo + TIL - 1;
    const int ylo = (tt & 31) * TIL, yhi = ylo + TIL - 1;

    const int4* __restrict__ bb = g_bb + b * NTRI;
    int* __restrict__ list = g_list + (size_t)gw * NTRI;

    int cnt = 0;
    for (int base = 0; base < NTRI; base += 32) {
        const int t = base + lane;
        bool ok = false;
        if (t < NTRI) {
            int4 B = bb[t];
            ok = (B.x <= xhi) && (B.y >= xlo) && (B.z <= yhi) && (B.w >= ylo);
        }
        unsigned m = __ballot_sync(0xffffffffu, ok);
        if (ok) list[cnt + __popc(m & ((1u << lane) - 1u))] = t;
        cnt += __popc(m);
    }
    if (lane == 0) g_cnt[gw] = cnt;
}

// ---------------------------------------------------------------------------
// Kernel 3: split-K gather. grid = (NTILE, NSEG, NBATCH), block = 64 (8x8 px).
// Segment s sums contiguous list entries [s*len, (s+1)*len) -> partial buffer.
// No atomics; segments later reduced in ascending order (deterministic).
// ---------------------------------------------------------------------------
__global__ void __launch_bounds__(64) gather_kernel()
{
    __shared__ float4 sQ[SEGCAP * 3];

    const int tt  = blockIdx.x;
    const int seg = blockIdx.y;
    const int b   = blockIdx.z;
    const int tid = threadIdx.x;

    const int gw  = b * NTILE + tt;
    const int cnt = g_cnt[gw];
    const int len = (cnt + NSEG - 1) / NSEG;
    const int s0  = seg * len;
    const int s1  = min(cnt, s0 + len);
    const int m   = s1 - s0;

    float acc = 0.0f;
    if (m > 0) {
        const int* __restrict__ list = g_list + (size_t)gw * NTRI + s0;
        for (int i = tid; i < m; i += 64) {
            const int t3 = (b * NTRI + list[i]) * 3;
            sQ[i*3+0] = g_q[t3+0];
            sQ[i*3+1] = g_q[t3+1];
            sQ[i*3+2] = g_q[t3+2];
        }
    }
    __syncthreads();

    if (m > 0) {
        const float fx = (float)((tt >> 5) * TIL + (tid >> 3));
        const float fy = (float)((tt & 31) * TIL + (tid & 7));
        #pragma unroll 4
        for (int i = 0; i < m; i++) {
            float4 q0 = sQ[i*3+0], q1 = sQ[i*3+1], q2 = sQ[i*3+2];
            float u0 = fmaxf(fmaf(q0.z, fy, fmaf(q0.y, fx, q0.x)), 0.0f);
            float u1 = fmaxf(fmaf(q1.y, fy, fmaf(q1.x, fx, q0.w)), 0.0f);
            float u2 = fmaxf(fmaf(q2.x, fy, fmaf(q1.w, fx, q1.z)), 0.0f);
            float d  = u0 * u1 * u2 - q2.y;
            if (d > 0.0f) acc += tanh_pade(d * q2.z);
        }
    }

    g_part[(((size_t)b * NSEG + seg) * NTILE + tt) * 64 + tid] = acc;
}

// ---------------------------------------------------------------------------
// Kernel 4: reduce the NSEG partials per pixel in fixed ascending order
// (=> overall ascending-triangle summation; deterministic) and write output.
// ---------------------------------------------------------------------------
__global__ void __launch_bounds__(256) reduce_kernel(float* __restrict__ out)
{
    const int j = blockIdx.x * blockDim.x + threadIdx.x;   // [0, NBATCH*NTILE*64)
    if (j >= NBATCH * NTILE * 64) return;
    const int b   = j / (NTILE * 64);
    const int r   = j - b * (NTILE * 64);
    const int tt  = r >> 6;
    const int tid = r & 63;

    float s = 0.0f;
    #pragma unroll
    for (int seg = 0; seg < NSEG; seg++)
        s += g_part[(((size_t)b * NSEG + seg) * NTILE + tt) * 64 + tid];

    const int px = (tt >> 5) * TIL + (tid >> 3);
    const int py = (tt & 31) * TIL + (tid & 7);
    out[(size_t)b * NPIX + px * RES + py] = s;
}

// ---------------------------------------------------------------------------
extern "C" void kernel_launch(void* const* d_in, const int* in_sizes, int n_in,
                              void* d_out, int out_size)
{
    const float* meshes = (const float*)d_in[0];
    const float* K      = (const float*)d_in[1];
    const int*   idxs   = (const int*)  d_in[2];
    const float* poses  = (const float*)d_in[3];
    float*       out    = (float*)d_out;

    setup_kernel<<<(NBT * 32 + 255) / 256, 256>>>(meshes, K, idxs, poses);
    bin_kernel<<<(NBATCH * NTILE * 32 + 255) / 256, 256>>>();

    dim3 g(NTILE, NSEG, NBATCH);
    gather_kernel<<<g, 64>>>();

    reduce_kernel<<<(NBATCH * NTILE * 64 + 255) / 256, 256>>>(out);
}